// round 3
// baseline (speedup 1.0000x reference)
#include <cuda_runtime.h>
#include <cuda_bf16.h>

// YOLO post-process:
//   in : (16, 25200, 85) f32 rows = [x, y, w, h, conf, cls0..cls79]
//   out: (16, 25200, 6)  f32 rows = [x-w/2, y-h/2, x+w/2, y+h/2, conf*max(cls), argmax(cls)]
//        zeroed where conf*max(cls) <= 0.25
//
// R3: the R2 kernel was L1TEX-wavefront bound (70.9%): each warp-LDG.32 of the
// interleaved mapping touched 8 rows -> ~8 wavefronts/instr. Now each block
// stages its contiguous 21760B tile (64 rows x 85 f32) through smem with
// LDG.128/STS.128 (fully coalesced, 4 wavefronts per warp-instr), then runs
// the same 4-lane-per-row reduction out of shared memory.

static constexpr int   ROWLEN        = 85;
static constexpr int   OUTLEN        = 6;
static constexpr int   ROWS_PER_WARP = 8;
static constexpr int   THREADS       = 256;
static constexpr int   ROWS_PER_BLK  = (THREADS / 32) * ROWS_PER_WARP;   // 64
static constexpr int   TILE_FLOATS   = ROWS_PER_BLK * ROWLEN;            // 5440
static constexpr int   TILE_F4       = TILE_FLOATS / 4;                  // 1360
static constexpr int   F4_FULL_ITERS = TILE_F4 / THREADS;                // 5
static constexpr int   F4_TAIL       = TILE_F4 - F4_FULL_ITERS * THREADS; // 80
static constexpr float CONF_THRESH   = 0.25f;
static constexpr float NEG_INF       = -1e30f;

__global__ __launch_bounds__(THREADS)
void yolo_post_kernel(const float4* __restrict__ in4,
                      float* __restrict__ out,
                      int nrows)
{
    __shared__ float tile[TILE_FLOATS];              // 21760 B, raw row-major
    __shared__ float s_out[ROWS_PER_BLK * OUTLEN];   // 1536 B

    const int tid = threadIdx.x;

    // ---- Stage tile: contiguous float4 loads, front-batched for MLP ----
    {
        const size_t base4 = (size_t)blockIdx.x * TILE_F4;
        float4 q[F4_FULL_ITERS];
        #pragma unroll
        for (int i = 0; i < F4_FULL_ITERS; i++)
            q[i] = in4[base4 + tid + i * THREADS];
        #pragma unroll
        for (int i = 0; i < F4_FULL_ITERS; i++)
            *reinterpret_cast<float4*>(&tile[4 * (tid + i * THREADS)]) = q[i];
        if (tid < F4_TAIL) {
            const int t = F4_FULL_ITERS * THREADS + tid;
            *reinterpret_cast<float4*>(&tile[4 * t]) = in4[base4 + t];
        }
    }
    __syncthreads();

    // ---- Compute: 4 threads per row, 8 rows per warp ----
    const int lane = tid & 31;
    const int wid  = tid >> 5;
    const int g    = lane >> 2;          // row subgroup within warp (0..7)
    const int j    = lane & 3;           // sub-lane within row group (0..3)

    const int rowloc = wid * ROWS_PER_WARP + g;            // 0..63
    const int row    = blockIdx.x * ROWS_PER_BLK + rowloc;

    if (row < nrows) {
        const float* rp = &tile[rowloc * ROWLEN];

        // Elements e = j + 4k for k = 0..20; e=84 handled by j==0.
        float v[22];
        #pragma unroll
        for (int k = 0; k < 21; k++)
            v[k] = rp[j + 4 * k];
        v[21] = (j == 0) ? rp[84] : NEG_INF;

        const float box = v[0];          // lane j holds box field j (x,y,w,h)

        // Per-lane max/argmax over class elements (e>=5); j==0 excludes
        // k=1 (e=4 is conf). Indices increase with k -> '>' keeps first-max.
        float m  = NEG_INF;
        int   mk = 1;
        #pragma unroll
        for (int k = 1; k < 22; k++) {
            float c = v[k];
            if (k == 1 && j == 0) c = NEG_INF;
            if (c > m) { m = c; mk = k; }
        }
        int ci = j + 4 * mk - 5;         // class index 0..79

        // Butterfly across the 4-lane group; (max, first index).
        #pragma unroll
        for (int off = 1; off <= 2; off <<= 1) {
            const float om = __shfl_xor_sync(0xffffffffu, m,  off);
            const int   oi = __shfl_xor_sync(0xffffffffu, ci, off);
            if (om > m || (om == m && oi < ci)) { m = om; ci = oi; }
        }

        // a = x (j even) / y (j odd); b = w (j even) / h (j odd)
        const int   base = lane & ~3;
        const float a    = __shfl_sync(0xffffffffu, box,  base + (j & 1));
        const float b    = __shfl_sync(0xffffffffu, box,  base + 2 + (j & 1));
        const float conf = __shfl_sync(0xffffffffu, v[1], base);

        const float score = conf * m;
        const bool  keep  = score > CONF_THRESH;

        const float sign = (j < 2) ? -0.5f : 0.5f;
        const float o    = fmaf(sign, b, a);

        float* srow = &s_out[rowloc * OUTLEN];
        srow[j] = keep ? o : 0.0f;
        if (j == 0) srow[4] = keep ? score : 0.0f;
        if (j == 1) srow[5] = keep ? (float)ci : 0.0f;
    }
    __syncthreads();

    // ---- Contiguous 1536B output store per block ----
    const size_t obase = (size_t)blockIdx.x * (ROWS_PER_BLK * OUTLEN);
    const size_t olim  = (size_t)nrows * OUTLEN;
    #pragma unroll
    for (int i = tid; i < ROWS_PER_BLK * OUTLEN; i += THREADS) {
        if (obase + i < olim)
            out[obase + i] = s_out[i];
    }
}

extern "C" void kernel_launch(void* const* d_in, const int* in_sizes, int n_in,
                              void* d_out, int out_size)
{
    const float4* in4 = (const float4*)d_in[0];
    float*        out = (float*)d_out;

    const int nrows  = out_size / OUTLEN;                         // 403200
    const int blocks = (nrows + ROWS_PER_BLK - 1) / ROWS_PER_BLK; // 6300

    yolo_post_kernel<<<blocks, THREADS>>>(in4, out, nrows);
}